// round 1
// baseline (speedup 1.0000x reference)
#include <cuda_runtime.h>
#include <math.h>

#define BT    8192
#define DIMV  1024
#define NQKV  3072
#define HEADS 16
#define DH    64
#define SEQT  2048
#define NBH   64          // 4 batches * 16 heads
#define ATTN_SMEM (4 * 64 * 68 * 4)   // Qs,Ks,Vs,Ps each [64][68] floats

// -------- scratch (device globals; no allocation allowed) --------
__device__ float g_xn[BT * DIMV];
__device__ float g_q [NBH * SEQT * DH];
__device__ float g_k [NBH * SEQT * DH];
__device__ float g_v [NBH * SEQT * DH];
__device__ float g_attn[BT * DIMV];

// ============================================================
// 1) LayerNorm: one block per row (1024 elems, 256 thr * float4)
// ============================================================
__global__ __launch_bounds__(256)
void ln_kernel(const float* __restrict__ x,
               const float* __restrict__ gamma,
               const float* __restrict__ beta) {
    int row = blockIdx.x;
    int tid = threadIdx.x;
    const float4 v = reinterpret_cast<const float4*>(x + (size_t)row * DIMV)[tid];
    float s  = v.x + v.y + v.z + v.w;
    float s2 = v.x*v.x + v.y*v.y + v.z*v.z + v.w*v.w;
#pragma unroll
    for (int off = 16; off; off >>= 1) {
        s  += __shfl_xor_sync(0xffffffffu, s,  off);
        s2 += __shfl_xor_sync(0xffffffffu, s2, off);
    }
    __shared__ float ss[8], ss2[8];
    if ((tid & 31) == 0) { ss[tid >> 5] = s; ss2[tid >> 5] = s2; }
    __syncthreads();
    float tot = 0.f, tot2 = 0.f;
#pragma unroll
    for (int w = 0; w < 8; w++) { tot += ss[w]; tot2 += ss2[w]; }
    float mu   = tot  * (1.f / 1024.f);
    float var  = tot2 * (1.f / 1024.f) - mu * mu;
    float rstd = rsqrtf(var + 1e-5f);
    const float4 g = reinterpret_cast<const float4*>(gamma)[tid];
    const float4 b = reinterpret_cast<const float4*>(beta)[tid];
    float4 o;
    o.x = (v.x - mu) * rstd * g.x + b.x;
    o.y = (v.y - mu) * rstd * g.y + b.y;
    o.z = (v.z - mu) * rstd * g.z + b.z;
    o.w = (v.w - mu) * rstd * g.w + b.w;
    reinterpret_cast<float4*>(g_xn + (size_t)row * DIMV)[tid] = o;
}

// ============================================================
// 2) QKV GEMM: g_xn[8192,1024] @ w_qkv[1024,3072]
//    128x128 tile, BK=16, 256 thr, 8x8 per thread (split 4+4)
//    Epilogue scatters to q/k/v in [b,h,t,d] layout; Q scaled 1/8.
// ============================================================
__global__ __launch_bounds__(256)
void qkv_kernel(const float* __restrict__ w) {
    __shared__ float As[16][128];
    __shared__ float Bs[16][128];
    int tid = threadIdx.x;
    int tx = tid & 15, ty = tid >> 4;
    int n0 = blockIdx.x * 128;
    int m0 = blockIdx.y * 128;
    float acc[8][8];
#pragma unroll
    for (int i = 0; i < 8; i++)
#pragma unroll
        for (int j = 0; j < 8; j++) acc[i][j] = 0.f;

    for (int k0 = 0; k0 < 1024; k0 += 16) {
#pragma unroll
        for (int l = 0; l < 2; l++) {
            int idx = tid * 2 + l;
            int ar = idx >> 2, akq = idx & 3;
            float4 av = *reinterpret_cast<const float4*>(
                g_xn + (size_t)(m0 + ar) * DIMV + k0 + akq * 4);
            As[akq*4+0][ar] = av.x; As[akq*4+1][ar] = av.y;
            As[akq*4+2][ar] = av.z; As[akq*4+3][ar] = av.w;
            int br = idx >> 5, bc = idx & 31;
            *reinterpret_cast<float4*>(&Bs[br][bc*4]) =
                *reinterpret_cast<const float4*>(w + (size_t)(k0 + br) * NQKV + n0 + bc * 4);
        }
        __syncthreads();
#pragma unroll
        for (int kk = 0; kk < 16; kk++) {
            float a[8], b[8];
            *reinterpret_cast<float4*>(a)   = *reinterpret_cast<float4*>(&As[kk][ty*4]);
            *reinterpret_cast<float4*>(a+4) = *reinterpret_cast<float4*>(&As[kk][64+ty*4]);
            *reinterpret_cast<float4*>(b)   = *reinterpret_cast<float4*>(&Bs[kk][tx*4]);
            *reinterpret_cast<float4*>(b+4) = *reinterpret_cast<float4*>(&Bs[kk][64+tx*4]);
#pragma unroll
            for (int i = 0; i < 8; i++)
#pragma unroll
                for (int j = 0; j < 8; j++) acc[i][j] = fmaf(a[i], b[j], acc[i][j]);
        }
        __syncthreads();
    }
    // epilogue: scatter into [b,h,t,d]
#pragma unroll
    for (int i = 0; i < 8; i++) {
        int ri = m0 + ((i < 4) ? (ty*4 + i) : (60 + ty*4 + i));
        int bb = ri >> 11;        // / 2048
        int t  = ri & 2047;
#pragma unroll
        for (int jg = 0; jg < 2; jg++) {
            int c0    = n0 + jg * 64 + tx * 4;
            int which = c0 >> 10;
            int cc    = c0 & 1023;
            int h     = cc >> 6;
            int d     = cc & 63;
            float* dst; float sc;
            if (which == 0)      { dst = g_q; sc = 0.125f; }  // fold softmax scale into Q
            else if (which == 1) { dst = g_k; sc = 1.0f; }
            else                 { dst = g_v; sc = 1.0f; }
            size_t off = (((size_t)(bb * HEADS + h)) * SEQT + t) * DH + d;
            float4 r;
            r.x = acc[i][jg*4+0] * sc;
            r.y = acc[i][jg*4+1] * sc;
            r.z = acc[i][jg*4+2] * sc;
            r.w = acc[i][jg*4+3] * sc;
            *reinterpret_cast<float4*>(dst + off) = r;
        }
    }
}

// ============================================================
// 3) Flash attention (fp32): block = 64 Q rows of one (b,h),
//    loops 32 KV tiles of 64. 256 thr = 16x16, 4x4 micro-tiles.
//    Online softmax; P staged via smem for P@V.
// ============================================================
__global__ __launch_bounds__(256)
void attn_kernel() {
    extern __shared__ float smem[];
    float* Qs = smem;               // [64][68]  (d, m)   transposed
    float* Ks = smem + 4352;        // [64][68]  (d, n)   transposed
    float* Vs = smem + 8704;        // [64][68]  (n, d)
    float* Ps = smem + 13056;       // [64][68]  (m, n)

    int bh = blockIdx.y;
    int m0 = blockIdx.x * 64;
    const float* Qp = g_q + (size_t)bh * SEQT * DH;
    const float* Kp = g_k + (size_t)bh * SEQT * DH;
    const float* Vp = g_v + (size_t)bh * SEQT * DH;

    int tid = threadIdx.x;
    int tx = tid & 15, ty = tid >> 4;

    // load Q tile transposed: Qs[d][m]
#pragma unroll
    for (int l = 0; l < 4; l++) {
        int idx = tid + 256 * l;          // 0..1023
        int m   = idx >> 4;
        int d4  = idx & 15;
        float4 qv = *reinterpret_cast<const float4*>(Qp + (size_t)(m0 + m) * DH + d4 * 4);
        Qs[(d4*4+0)*68 + m] = qv.x; Qs[(d4*4+1)*68 + m] = qv.y;
        Qs[(d4*4+2)*68 + m] = qv.z; Qs[(d4*4+3)*68 + m] = qv.w;
    }

    float o[4][4];
    float mprev[4], lsum[4];
#pragma unroll
    for (int i = 0; i < 4; i++) {
        mprev[i] = -INFINITY; lsum[i] = 0.f;
#pragma unroll
        for (int j = 0; j < 4; j++) o[i][j] = 0.f;
    }

    for (int jt = 0; jt < 32; jt++) {
        int j0 = jt * 64;
        __syncthreads();   // previous O-phase done reading Ps/Vs
        // load K transposed, V natural
#pragma unroll
        for (int l = 0; l < 4; l++) {
            int idx = tid + 256 * l;
            int n   = idx >> 4;
            int d4  = idx & 15;
            float4 kv = *reinterpret_cast<const float4*>(Kp + (size_t)(j0 + n) * DH + d4 * 4);
            Ks[(d4*4+0)*68 + n] = kv.x; Ks[(d4*4+1)*68 + n] = kv.y;
            Ks[(d4*4+2)*68 + n] = kv.z; Ks[(d4*4+3)*68 + n] = kv.w;
            float4 vv = *reinterpret_cast<const float4*>(Vp + (size_t)(j0 + n) * DH + d4 * 4);
            *reinterpret_cast<float4*>(&Vs[n*68 + d4*4]) = vv;
        }
        __syncthreads();

        // S = Q @ K^T  (Q pre-scaled by 1/8)
        float s[4][4];
#pragma unroll
        for (int i = 0; i < 4; i++)
#pragma unroll
            for (int j = 0; j < 4; j++) s[i][j] = 0.f;
#pragma unroll 8
        for (int kk = 0; kk < 64; kk++) {
            float a[4], b[4];
            *reinterpret_cast<float4*>(a) = *reinterpret_cast<float4*>(&Qs[kk*68 + ty*4]);
            *reinterpret_cast<float4*>(b) = *reinterpret_cast<float4*>(&Ks[kk*68 + tx*4]);
#pragma unroll
            for (int i = 0; i < 4; i++)
#pragma unroll
                for (int j = 0; j < 4; j++) s[i][j] = fmaf(a[i], b[j], s[i][j]);
        }

        // online softmax (row reduce over the 16 tx lanes = half-warp)
        float mx[4], rs[4], alpha[4];
#pragma unroll
        for (int i = 0; i < 4; i++)
            mx[i] = fmaxf(fmaxf(s[i][0], s[i][1]), fmaxf(s[i][2], s[i][3]));
#pragma unroll
        for (int off = 8; off; off >>= 1)
#pragma unroll
            for (int i = 0; i < 4; i++)
                mx[i] = fmaxf(mx[i], __shfl_xor_sync(0xffffffffu, mx[i], off));
#pragma unroll
        for (int i = 0; i < 4; i++) {
            float mn = fmaxf(mprev[i], mx[i]);
            alpha[i] = __expf(mprev[i] - mn);
            mprev[i] = mn;
            float r = 0.f;
#pragma unroll
            for (int j = 0; j < 4; j++) { s[i][j] = __expf(s[i][j] - mn); r += s[i][j]; }
            rs[i] = r;
        }
#pragma unroll
        for (int off = 8; off; off >>= 1)
#pragma unroll
            for (int i = 0; i < 4; i++)
                rs[i] += __shfl_xor_sync(0xffffffffu, rs[i], off);
#pragma unroll
        for (int i = 0; i < 4; i++) {
            lsum[i] = lsum[i] * alpha[i] + rs[i];
#pragma unroll
            for (int j = 0; j < 4; j++) o[i][j] *= alpha[i];
            // stage P row
            *reinterpret_cast<float4*>(&Ps[(ty*4+i)*68 + tx*4]) =
                make_float4(s[i][0], s[i][1], s[i][2], s[i][3]);
        }
        __syncthreads();

        // O += P @ V
#pragma unroll 8
        for (int n = 0; n < 64; n++) {
            float vv[4];
            *reinterpret_cast<float4*>(vv) = *reinterpret_cast<float4*>(&Vs[n*68 + tx*4]);
            float p0 = Ps[(ty*4+0)*68 + n];
            float p1 = Ps[(ty*4+1)*68 + n];
            float p2 = Ps[(ty*4+2)*68 + n];
            float p3 = Ps[(ty*4+3)*68 + n];
#pragma unroll
            for (int j = 0; j < 4; j++) {
                o[0][j] = fmaf(p0, vv[j], o[0][j]);
                o[1][j] = fmaf(p1, vv[j], o[1][j]);
                o[2][j] = fmaf(p2, vv[j], o[2][j]);
                o[3][j] = fmaf(p3, vv[j], o[3][j]);
            }
        }
    }

    // epilogue: normalize and write to [b, t, h*64+d]
    int bb = bh >> 4, h = bh & 15;
#pragma unroll
    for (int i = 0; i < 4; i++) {
        float inv = 1.f / lsum[i];
        int t = m0 + ty*4 + i;
        size_t off = ((size_t)(bb * SEQT + t)) * DIMV + h * DH + tx * 4;
        float4 r;
        r.x = o[i][0] * inv; r.y = o[i][1] * inv;
        r.z = o[i][2] * inv; r.w = o[i][3] * inv;
        *reinterpret_cast<float4*>(g_attn + off) = r;
    }
}

// ============================================================
// 4) Out projection: g_attn[8192,1024] @ w_out[1024,1024] + b_out
// ============================================================
__global__ __launch_bounds__(256)
void out_kernel(const float* __restrict__ w,
                const float* __restrict__ bias,
                float* __restrict__ out) {
    __shared__ float As[16][128];
    __shared__ float Bs[16][128];
    int tid = threadIdx.x;
    int tx = tid & 15, ty = tid >> 4;
    int n0 = blockIdx.x * 128;
    int m0 = blockIdx.y * 128;
    float acc[8][8];
#pragma unroll
    for (int i = 0; i < 8; i++)
#pragma unroll
        for (int j = 0; j < 8; j++) acc[i][j] = 0.f;

    for (int k0 = 0; k0 < 1024; k0 += 16) {
#pragma unroll
        for (int l = 0; l < 2; l++) {
            int idx = tid * 2 + l;
            int ar = idx >> 2, akq = idx & 3;
            float4 av = *reinterpret_cast<const float4*>(
                g_attn + (size_t)(m0 + ar) * DIMV + k0 + akq * 4);
            As[akq*4+0][ar] = av.x; As[akq*4+1][ar] = av.y;
            As[akq*4+2][ar] = av.z; As[akq*4+3][ar] = av.w;
            int br = idx >> 5, bc = idx & 31;
            *reinterpret_cast<float4*>(&Bs[br][bc*4]) =
                *reinterpret_cast<const float4*>(w + (size_t)(k0 + br) * DIMV + n0 + bc * 4);
        }
        __syncthreads();
#pragma unroll
        for (int kk = 0; kk < 16; kk++) {
            float a[8], b[8];
            *reinterpret_cast<float4*>(a)   = *reinterpret_cast<float4*>(&As[kk][ty*4]);
            *reinterpret_cast<float4*>(a+4) = *reinterpret_cast<float4*>(&As[kk][64+ty*4]);
            *reinterpret_cast<float4*>(b)   = *reinterpret_cast<float4*>(&Bs[kk][tx*4]);
            *reinterpret_cast<float4*>(b+4) = *reinterpret_cast<float4*>(&Bs[kk][64+tx*4]);
#pragma unroll
            for (int i = 0; i < 8; i++)
#pragma unroll
                for (int j = 0; j < 8; j++) acc[i][j] = fmaf(a[i], b[j], acc[i][j]);
        }
        __syncthreads();
    }
#pragma unroll
    for (int i = 0; i < 8; i++) {
        int ri = m0 + ((i < 4) ? (ty*4 + i) : (60 + ty*4 + i));
#pragma unroll
        for (int jg = 0; jg < 2; jg++) {
            int c0 = n0 + jg * 64 + tx * 4;
            float4 r;
            r.x = acc[i][jg*4+0] + bias[c0+0];
            r.y = acc[i][jg*4+1] + bias[c0+1];
            r.z = acc[i][jg*4+2] + bias[c0+2];
            r.w = acc[i][jg*4+3] + bias[c0+3];
            *reinterpret_cast<float4*>(out + (size_t)ri * DIMV + c0) = r;
        }
    }
}

// ============================================================
extern "C" void kernel_launch(void* const* d_in, const int* in_sizes, int n_in,
                              void* d_out, int out_size) {
    const float* x     = (const float*)d_in[0];
    const float* gamma = (const float*)d_in[1];
    const float* beta  = (const float*)d_in[2];
    const float* w_qkv = (const float*)d_in[3];
    const float* w_out = (const float*)d_in[4];
    const float* b_out = (const float*)d_in[5];
    float* out = (float*)d_out;

    ln_kernel<<<BT, 256>>>(x, gamma, beta);
    qkv_kernel<<<dim3(NQKV / 128, BT / 128), 256>>>(w_qkv);
    cudaFuncSetAttribute(attn_kernel, cudaFuncAttributeMaxDynamicSharedMemorySize, ATTN_SMEM);
    attn_kernel<<<dim3(SEQT / 64, NBH), 256, ATTN_SMEM>>>();
    out_kernel<<<dim3(DIMV / 128, BT / 128), 256>>>(w_out, b_out, out);
}

// round 2
// speedup vs baseline: 2.9321x; 2.9321x over previous
#include <cuda_runtime.h>
#include <math.h>

#define BT    8192
#define DIMV  1024
#define NQKV  3072
#define HEADS 16
#define DH    64
#define SEQT  2048
#define NBH   64
#define ATTN_SMEM 70656   // Qs[64][68] + Ks[64][68] + Ps[64][68] + Vs[64][72] floats

// -------- scratch (device globals; no allocation allowed) --------
__device__ float g_xn[BT * DIMV];
__device__ float g_q [NBH * SEQT * DH];
__device__ float g_k [NBH * SEQT * DH];
__device__ float g_v [NBH * SEQT * DH];
__device__ float g_attn[BT * DIMV];

// ---------------- tf32 helpers ----------------
__device__ __forceinline__ float f2tf(float x) {
    unsigned u;
    asm("cvt.rna.tf32.f32 %0, %1;" : "=r"(u) : "f"(x));
    return __uint_as_float(u);
}

__device__ __forceinline__ void mma_tf32(float c[4],
                                         unsigned a0, unsigned a1, unsigned a2, unsigned a3,
                                         unsigned b0, unsigned b1) {
    asm volatile(
        "mma.sync.aligned.m16n8k8.row.col.f32.tf32.tf32.f32 "
        "{%0,%1,%2,%3},{%4,%5,%6,%7},{%8,%9},{%0,%1,%2,%3};"
        : "+f"(c[0]), "+f"(c[1]), "+f"(c[2]), "+f"(c[3])
        : "r"(a0), "r"(a1), "r"(a2), "r"(a3), "r"(b0), "r"(b1));
}

// ============================================================
// 1) LayerNorm (output rounded to tf32 — it feeds the QKV mma)
// ============================================================
__global__ __launch_bounds__(256)
void ln_kernel(const float* __restrict__ x,
               const float* __restrict__ gamma,
               const float* __restrict__ beta) {
    int row = blockIdx.x;
    int tid = threadIdx.x;
    const float4 v = reinterpret_cast<const float4*>(x + (size_t)row * DIMV)[tid];
    float s  = v.x + v.y + v.z + v.w;
    float s2 = v.x*v.x + v.y*v.y + v.z*v.z + v.w*v.w;
#pragma unroll
    for (int off = 16; off; off >>= 1) {
        s  += __shfl_xor_sync(0xffffffffu, s,  off);
        s2 += __shfl_xor_sync(0xffffffffu, s2, off);
    }
    __shared__ float ss[8], ss2[8];
    if ((tid & 31) == 0) { ss[tid >> 5] = s; ss2[tid >> 5] = s2; }
    __syncthreads();
    float tot = 0.f, tot2 = 0.f;
#pragma unroll
    for (int w = 0; w < 8; w++) { tot += ss[w]; tot2 += ss2[w]; }
    float mu   = tot  * (1.f / 1024.f);
    float var  = tot2 * (1.f / 1024.f) - mu * mu;
    float rstd = rsqrtf(var + 1e-5f);
    const float4 g = reinterpret_cast<const float4*>(gamma)[tid];
    const float4 b = reinterpret_cast<const float4*>(beta)[tid];
    float4 o;
    o.x = f2tf((v.x - mu) * rstd * g.x + b.x);
    o.y = f2tf((v.y - mu) * rstd * g.y + b.y);
    o.z = f2tf((v.z - mu) * rstd * g.z + b.z);
    o.w = f2tf((v.w - mu) * rstd * g.w + b.w);
    reinterpret_cast<float4*>(g_xn + (size_t)row * DIMV)[tid] = o;
}

// ============================================================
// 2) QKV GEMM via tf32 mma: g_xn[8192,1024] @ w_qkv[1024,3072]
//    128x128 tile, BK=32, 256 thr = 8 warps (2m x 4n),
//    each warp 4 m16-tiles x 4 n8-tiles. Scatter to [b,h,t,d].
// ============================================================
__global__ __launch_bounds__(256)
void qkv_kernel(const float* __restrict__ w) {
    __shared__ float As[128][36];   // [m][k], stride 36 -> frag banks 4g+r
    __shared__ float Bs[32][136];   // [k][n], stride 136 -> frag banks 8r+g
    int tid  = threadIdx.x;
    int lane = tid & 31, wid = tid >> 5;
    int g = lane >> 2, r = lane & 3;
    int warp_m = wid >> 2, warp_n = wid & 3;
    int m0 = blockIdx.y * 128, n0 = blockIdx.x * 128;
    int moff = warp_m * 64, noff = warp_n * 32;

    float c[4][4][4];
#pragma unroll
    for (int mt = 0; mt < 4; mt++)
#pragma unroll
        for (int nt = 0; nt < 4; nt++)
#pragma unroll
            for (int j = 0; j < 4; j++) c[mt][nt][j] = 0.f;

    for (int k0 = 0; k0 < 1024; k0 += 32) {
#pragma unroll
        for (int l = 0; l < 4; l++) {
            int idx = tid + 256 * l;
            int m = idx >> 3, c4 = idx & 7;
            float4 av = *reinterpret_cast<const float4*>(
                g_xn + (size_t)(m0 + m) * DIMV + k0 + 4 * c4);
            *reinterpret_cast<float4*>(&As[m][4 * c4]) = av;
        }
#pragma unroll
        for (int l = 0; l < 4; l++) {
            int idx = tid + 256 * l;
            int kr = idx >> 5, c4 = idx & 31;
            float4 bv = *reinterpret_cast<const float4*>(
                w + (size_t)(k0 + kr) * NQKV + n0 + 4 * c4);
            bv.x = f2tf(bv.x); bv.y = f2tf(bv.y);
            bv.z = f2tf(bv.z); bv.w = f2tf(bv.w);
            *reinterpret_cast<float4*>(&Bs[kr][4 * c4]) = bv;
        }
        __syncthreads();
#pragma unroll
        for (int ks = 0; ks < 4; ks++) {
            int kk = ks * 8;
            unsigned a[4][4], b[4][2];
#pragma unroll
            for (int mt = 0; mt < 4; mt++) {
                int row = moff + mt * 16 + g;
                a[mt][0] = __float_as_uint(As[row    ][kk + r    ]);
                a[mt][1] = __float_as_uint(As[row + 8][kk + r    ]);
                a[mt][2] = __float_as_uint(As[row    ][kk + r + 4]);
                a[mt][3] = __float_as_uint(As[row + 8][kk + r + 4]);
            }
#pragma unroll
            for (int nt = 0; nt < 4; nt++) {
                int col = noff + nt * 8 + g;
                b[nt][0] = __float_as_uint(Bs[kk + r    ][col]);
                b[nt][1] = __float_as_uint(Bs[kk + r + 4][col]);
            }
#pragma unroll
            for (int mt = 0; mt < 4; mt++)
#pragma unroll
                for (int nt = 0; nt < 4; nt++)
                    mma_tf32(c[mt][nt], a[mt][0], a[mt][1], a[mt][2], a[mt][3],
                             b[nt][0], b[nt][1]);
        }
        __syncthreads();
    }

    // epilogue: scatter into q/k/v [b,h,t,d], fold 1/8 into Q, round to tf32
#pragma unroll
    for (int mt = 0; mt < 4; mt++) {
        int ri0 = m0 + moff + mt * 16 + g;
        int ri1 = ri0 + 8;
        int bb0 = ri0 >> 11, t0 = ri0 & 2047;
        int bb1 = ri1 >> 11, t1 = ri1 & 2047;
#pragma unroll
        for (int nt = 0; nt < 4; nt++) {
            int col = n0 + noff + nt * 8 + 2 * r;
            int which = col >> 10;
            int cc = col & 1023;
            int h = cc >> 6, d = cc & 63;
            float sc = (which == 0) ? 0.125f : 1.0f;
            float* dst = (which == 0) ? g_q : ((which == 1) ? g_k : g_v);
            size_t o0 = (((size_t)(bb0 * HEADS + h)) * SEQT + t0) * DH + d;
            size_t o1 = (((size_t)(bb1 * HEADS + h)) * SEQT + t1) * DH + d;
            float2 v0 = make_float2(f2tf(c[mt][nt][0] * sc), f2tf(c[mt][nt][1] * sc));
            float2 v1 = make_float2(f2tf(c[mt][nt][2] * sc), f2tf(c[mt][nt][3] * sc));
            *reinterpret_cast<float2*>(dst + o0) = v0;
            *reinterpret_cast<float2*>(dst + o1) = v1;
        }
    }
}

// ============================================================
// 3) Flash attention, tf32 mma. Block = 64 Q rows, 4 warps
//    (16 rows each). 32 KV tiles of 64. Online softmax.
// ============================================================
__global__ __launch_bounds__(128)
void attn_kernel() {
    extern __shared__ float sm[];
    float* Qs = sm;                // [64][68]
    float* Ks = sm + 64 * 68;      // [64][68]
    float* Ps = sm + 2 * 64 * 68;  // [64][68]
    float* Vs = sm + 3 * 64 * 68;  // [64][72]

    int bh = blockIdx.y;
    int m0 = blockIdx.x * 64;
    const float* Qp = g_q + (size_t)bh * SEQT * DH;
    const float* Kp = g_k + (size_t)bh * SEQT * DH;
    const float* Vp = g_v + (size_t)bh * SEQT * DH;

    int tid  = threadIdx.x;
    int lane = tid & 31, w = tid >> 5;
    int g = lane >> 2, r = lane & 3;
    int arow = w * 16 + g;

    // load Q tile [64][64]
#pragma unroll
    for (int l = 0; l < 8; l++) {
        int idx = tid + 128 * l;
        int m = idx >> 4, c4 = idx & 15;
        *reinterpret_cast<float4*>(&Qs[m * 68 + 4 * c4]) =
            *reinterpret_cast<const float4*>(Qp + (size_t)(m0 + m) * DH + 4 * c4);
    }

    float o[8][4];
#pragma unroll
    for (int nt = 0; nt < 8; nt++)
#pragma unroll
        for (int j = 0; j < 4; j++) o[nt][j] = 0.f;
    float m_lo = -INFINITY, m_hi = -INFINITY, l_lo = 0.f, l_hi = 0.f;

    for (int jt = 0; jt < 32; jt++) {
        __syncthreads();   // prev iter done reading Ks/Vs
        int j0 = jt * 64;
#pragma unroll
        for (int l = 0; l < 8; l++) {
            int idx = tid + 128 * l;
            int n = idx >> 4, c4 = idx & 15;
            *reinterpret_cast<float4*>(&Ks[n * 68 + 4 * c4]) =
                *reinterpret_cast<const float4*>(Kp + (size_t)(j0 + n) * DH + 4 * c4);
            *reinterpret_cast<float4*>(&Vs[n * 72 + 4 * c4]) =
                *reinterpret_cast<const float4*>(Vp + (size_t)(j0 + n) * DH + 4 * c4);
        }
        __syncthreads();

        // S = Q @ K^T : per warp 16x64
        float s[8][4];
#pragma unroll
        for (int nt = 0; nt < 8; nt++)
#pragma unroll
            for (int j = 0; j < 4; j++) s[nt][j] = 0.f;
#pragma unroll
        for (int ks = 0; ks < 8; ks++) {
            int kk = ks * 8;
            unsigned a0 = __float_as_uint(Qs[arow * 68 + kk + r]);
            unsigned a1 = __float_as_uint(Qs[(arow + 8) * 68 + kk + r]);
            unsigned a2 = __float_as_uint(Qs[arow * 68 + kk + r + 4]);
            unsigned a3 = __float_as_uint(Qs[(arow + 8) * 68 + kk + r + 4]);
#pragma unroll
            for (int nt = 0; nt < 8; nt++) {
                unsigned b0 = __float_as_uint(Ks[(nt * 8 + g) * 68 + kk + r]);
                unsigned b1 = __float_as_uint(Ks[(nt * 8 + g) * 68 + kk + r + 4]);
                mma_tf32(s[nt], a0, a1, a2, a3, b0, b1);
            }
        }

        // online softmax (rows lo = arow, hi = arow+8; reduce over quad lanes)
        float mx_lo = -INFINITY, mx_hi = -INFINITY;
#pragma unroll
        for (int nt = 0; nt < 8; nt++) {
            mx_lo = fmaxf(mx_lo, fmaxf(s[nt][0], s[nt][1]));
            mx_hi = fmaxf(mx_hi, fmaxf(s[nt][2], s[nt][3]));
        }
        mx_lo = fmaxf(mx_lo, __shfl_xor_sync(0xffffffffu, mx_lo, 1));
        mx_lo = fmaxf(mx_lo, __shfl_xor_sync(0xffffffffu, mx_lo, 2));
        mx_hi = fmaxf(mx_hi, __shfl_xor_sync(0xffffffffu, mx_hi, 1));
        mx_hi = fmaxf(mx_hi, __shfl_xor_sync(0xffffffffu, mx_hi, 2));
        float mn_lo = fmaxf(m_lo, mx_lo), mn_hi = fmaxf(m_hi, mx_hi);
        float al_lo = __expf(m_lo - mn_lo), al_hi = __expf(m_hi - mn_hi);
        m_lo = mn_lo; m_hi = mn_hi;
        float rs_lo = 0.f, rs_hi = 0.f;
#pragma unroll
        for (int nt = 0; nt < 8; nt++) {
            s[nt][0] = __expf(s[nt][0] - mn_lo);
            s[nt][1] = __expf(s[nt][1] - mn_lo);
            s[nt][2] = __expf(s[nt][2] - mn_hi);
            s[nt][3] = __expf(s[nt][3] - mn_hi);
            rs_lo += s[nt][0] + s[nt][1];
            rs_hi += s[nt][2] + s[nt][3];
        }
        rs_lo += __shfl_xor_sync(0xffffffffu, rs_lo, 1);
        rs_lo += __shfl_xor_sync(0xffffffffu, rs_lo, 2);
        rs_hi += __shfl_xor_sync(0xffffffffu, rs_hi, 1);
        rs_hi += __shfl_xor_sync(0xffffffffu, rs_hi, 2);
        l_lo = l_lo * al_lo + rs_lo;
        l_hi = l_hi * al_hi + rs_hi;
#pragma unroll
        for (int nt = 0; nt < 8; nt++) {
            o[nt][0] *= al_lo; o[nt][1] *= al_lo;
            o[nt][2] *= al_hi; o[nt][3] *= al_hi;
            *reinterpret_cast<float2*>(&Ps[arow * 68 + nt * 8 + 2 * r]) =
                make_float2(f2tf(s[nt][0]), f2tf(s[nt][1]));
            *reinterpret_cast<float2*>(&Ps[(arow + 8) * 68 + nt * 8 + 2 * r]) =
                make_float2(f2tf(s[nt][2]), f2tf(s[nt][3]));
        }
        __syncwarp();   // P rows are warp-private; warp-level ordering suffices

        // O += P @ V : per warp 16x64, k = 64
#pragma unroll
        for (int ks = 0; ks < 8; ks++) {
            int kk = ks * 8;
            unsigned a0 = __float_as_uint(Ps[arow * 68 + kk + r]);
            unsigned a1 = __float_as_uint(Ps[(arow + 8) * 68 + kk + r]);
            unsigned a2 = __float_as_uint(Ps[arow * 68 + kk + r + 4]);
            unsigned a3 = __float_as_uint(Ps[(arow + 8) * 68 + kk + r + 4]);
#pragma unroll
            for (int nt = 0; nt < 8; nt++) {
                unsigned b0 = __float_as_uint(Vs[(kk + r) * 72 + nt * 8 + g]);
                unsigned b1 = __float_as_uint(Vs[(kk + r + 4) * 72 + nt * 8 + g]);
                mma_tf32(o[nt], a0, a1, a2, a3, b0, b1);
            }
        }
    }

    // epilogue: normalize, round to tf32 (feeds out-proj mma), write [b,t,h*64+d]
    float inv_lo = 1.f / l_lo, inv_hi = 1.f / l_hi;
    int bb = bh >> 4, h = bh & 15;
    int t_lo = m0 + w * 16 + g, t_hi = t_lo + 8;
#pragma unroll
    for (int nt = 0; nt < 8; nt++) {
        int d0 = h * DH + nt * 8 + 2 * r;
        *reinterpret_cast<float2*>(g_attn + ((size_t)(bb * SEQT + t_lo)) * DIMV + d0) =
            make_float2(f2tf(o[nt][0] * inv_lo), f2tf(o[nt][1] * inv_lo));
        *reinterpret_cast<float2*>(g_attn + ((size_t)(bb * SEQT + t_hi)) * DIMV + d0) =
            make_float2(f2tf(o[nt][2] * inv_hi), f2tf(o[nt][3] * inv_hi));
    }
}

// ============================================================
// 4) Out projection via tf32 mma: g_attn[8192,1024] @ w_out[1024,1024] + b
// ============================================================
__global__ __launch_bounds__(256)
void out_kernel(const float* __restrict__ w,
                const float* __restrict__ bias,
                float* __restrict__ out) {
    __shared__ float As[128][36];
    __shared__ float Bs[32][136];
    int tid  = threadIdx.x;
    int lane = tid & 31, wid = tid >> 5;
    int g = lane >> 2, r = lane & 3;
    int warp_m = wid >> 2, warp_n = wid & 3;
    int m0 = blockIdx.y * 128, n0 = blockIdx.x * 128;
    int moff = warp_m * 64, noff = warp_n * 32;

    float c[4][4][4];
#pragma unroll
    for (int mt = 0; mt < 4; mt++)
#pragma unroll
        for (int nt = 0; nt < 4; nt++)
#pragma unroll
            for (int j = 0; j < 4; j++) c[mt][nt][j] = 0.f;

    for (int k0 = 0; k0 < 1024; k0 += 32) {
#pragma unroll
        for (int l = 0; l < 4; l++) {
            int idx = tid + 256 * l;
            int m = idx >> 3, c4 = idx & 7;
            *reinterpret_cast<float4*>(&As[m][4 * c4]) =
                *reinterpret_cast<const float4*>(
                    g_attn + (size_t)(m0 + m) * DIMV + k0 + 4 * c4);
        }
#pragma unroll
        for (int l = 0; l < 4; l++) {
            int idx = tid + 256 * l;
            int kr = idx >> 5, c4 = idx & 31;
            float4 bv = *reinterpret_cast<const float4*>(
                w + (size_t)(k0 + kr) * DIMV + n0 + 4 * c4);
            bv.x = f2tf(bv.x); bv.y = f2tf(bv.y);
            bv.z = f2tf(bv.z); bv.w = f2tf(bv.w);
            *reinterpret_cast<float4*>(&Bs[kr][4 * c4]) = bv;
        }
        __syncthreads();
#pragma unroll
        for (int ks = 0; ks < 4; ks++) {
            int kk = ks * 8;
            unsigned a[4][4], b[4][2];
#pragma unroll
            for (int mt = 0; mt < 4; mt++) {
                int row = moff + mt * 16 + g;
                a[mt][0] = __float_as_uint(As[row    ][kk + r    ]);
                a[mt][1] = __float_as_uint(As[row + 8][kk + r    ]);
                a[mt][2] = __float_as_uint(As[row    ][kk + r + 4]);
                a[mt][3] = __float_as_uint(As[row + 8][kk + r + 4]);
            }
#pragma unroll
            for (int nt = 0; nt < 4; nt++) {
                int col = noff + nt * 8 + g;
                b[nt][0] = __float_as_uint(Bs[kk + r    ][col]);
                b[nt][1] = __float_as_uint(Bs[kk + r + 4][col]);
            }
#pragma unroll
            for (int mt = 0; mt < 4; mt++)
#pragma unroll
                for (int nt = 0; nt < 4; nt++)
                    mma_tf32(c[mt][nt], a[mt][0], a[mt][1], a[mt][2], a[mt][3],
                             b[nt][0], b[nt][1]);
        }
        __syncthreads();
    }

#pragma unroll
    for (int mt = 0; mt < 4; mt++) {
        int ri0 = m0 + moff + mt * 16 + g;
        int ri1 = ri0 + 8;
#pragma unroll
        for (int nt = 0; nt < 4; nt++) {
            int col = n0 + noff + nt * 8 + 2 * r;
            float2 bb = *reinterpret_cast<const float2*>(bias + col);
            float2 v0 = make_float2(c[mt][nt][0] + bb.x, c[mt][nt][1] + bb.y);
            float2 v1 = make_float2(c[mt][nt][2] + bb.x, c[mt][nt][3] + bb.y);
            *reinterpret_cast<float2*>(out + (size_t)ri0 * DIMV + col) = v0;
            *reinterpret_cast<float2*>(out + (size_t)ri1 * DIMV + col) = v1;
        }
    }
}

// ============================================================
extern "C" void kernel_launch(void* const* d_in, const int* in_sizes, int n_in,
                              void* d_out, int out_size) {
    const float* x     = (const float*)d_in[0];
    const float* gamma = (const float*)d_in[1];
    const float* beta  = (const float*)d_in[2];
    const float* w_qkv = (const float*)d_in[3];
    const float* w_out = (const float*)d_in[4];
    const float* b_out = (const float*)d_in[5];
    float* out = (float*)d_out;

    ln_kernel<<<BT, 256>>>(x, gamma, beta);
    qkv_kernel<<<dim3(NQKV / 128, BT / 128), 256>>>(w_qkv);
    cudaFuncSetAttribute(attn_kernel, cudaFuncAttributeMaxDynamicSharedMemorySize, ATTN_SMEM);
    attn_kernel<<<dim3(SEQT / 64, NBH), 128, ATTN_SMEM>>>();
    out_kernel<<<dim3(DIMV / 128, BT / 128), 256>>>(w_out, b_out, out);
}